// round 10
// baseline (speedup 1.0000x reference)
#include <cuda_runtime.h>
#include <cstdint>

// OcrEmbedding: out[b,t,:] = sum_{s=0..3, id!=0} table[id[b,t,s], :]
// B=32, T=512, S=4, D=256, V=50000.
// d_in[0] = subtoken_ids (int32, B*T*S), d_in[1] = table (float32, V*D)
// Output: float32, B*T*D.
//
// LDG.32 experiment: previous kernels used LDG.128 (4 L1tex wavefronts per
// LDG at the 2.07 cyc/wf within-LDG replay rate). Here: one CTA (256 thr)
// per token row, one float per thread -> every table LDG is a single
// coalesced 128B line per warp (1 wavefront at the 1.0 cyc/wf cross-LDG
// rate). Tests whether wavefront-replay ingestion, not the outstanding-line
// cap, throttles the random-gather path.

#define BT (32 * 512)    // 16384 token rows
#define D  256

__global__ __launch_bounds__(D) void ocr_embed_ldg32_kernel(
    const int* __restrict__ ids,          // [BT*4]
    const float* __restrict__ table,      // [V*256]
    float* __restrict__ out)              // [BT*256]
{
    const int row = blockIdx.x;           // one CTA per token row
    const int t   = threadIdx.x;          // 0..255: float within D

    const int4 id = __ldg((const int4*)(ids + row * 4));  // warp-broadcast

    float s = 0.f;
    if (id.x != 0) s += __ldg(table + (size_t)id.x * D + t);
    if (id.y != 0) s += __ldg(table + (size_t)id.y * D + t);
    if (id.z != 0) s += __ldg(table + (size_t)id.z * D + t);
    if (id.w != 0) s += __ldg(table + (size_t)id.w * D + t);

    out[(size_t)row * D + t] = s;
}

extern "C" void kernel_launch(void* const* d_in, const int* in_sizes, int n_in,
                              void* d_out, int out_size)
{
    const int*   ids   = (const int*)d_in[0];
    const float* table = (const float*)d_in[1];
    float*       out   = (float*)d_out;

    ocr_embed_ldg32_kernel<<<BT, D>>>(ids, table, out);
}